// round 9
// baseline (speedup 1.0000x reference)
#include <cuda_runtime.h>
#include <cuda_bf16.h>

// IF spiking neuron forward (non-align, T>0):
//   x: [T, B, 1024, 3072] fp32 (flattened T*B), thresh2/dtmem: [1024,3072]
//   mem0 = dtmem*thre; per t: mem += x_t; spike = (mem>=thre)?thre:0; mem -= spike
//
// R9 = R7 (best measured: 118.8us, 6536 GB/s) with launch_bounds raised
// (256,6) -> (256,8). regs=32 allows exactly 8 blocks/SM (65536 regs);
// the ",6" was self-imposed and capped occupancy at 48/64 warps. 64 warps x
// 4 front-batched loads raises in-flight DRAM lines/SM ~33% while KEEPING
// per-thread MLP (unlike R5's high-occ/1-load shape that lost BW).
// Body identical to R7: batch in low 3 bid bits (L2 param co-residence),
// all 4 t-loads before the compute recurrence, streaming hints.

#define T_STEPS 4
#define B_BATCH 8
#define FEAT_N  (1024u * 3072u)       // 3,145,728 feature elements
#define N4      (FEAT_N / 4u)         // 786,432 float4 per feature map

__global__ __launch_bounds__(256, 8) void if_fwd_kernel(
    const float4* __restrict__ x,
    const float4* __restrict__ thresh,
    const float4* __restrict__ dtm,
    float4* __restrict__ out)
{
    const unsigned bid = blockIdx.x;
    const unsigned b   = bid & 7u;                          // batch index 0..7
    const unsigned f   = (bid >> 3) * 256u + threadIdx.x;   // feature float4 index
    if (f >= N4) return;

    const size_t tstride = (size_t)B_BATCH * N4;
    const float4* __restrict__ xp = x   + (size_t)b * N4 + f;
    float4* __restrict__       op = out + (size_t)b * N4 + f;

    // Front-batch ALL timestep loads (address-independent; only the membrane
    // recurrence is sequential, and that's pure compute).
    float4 xv0 = __ldcs(xp);
    float4 xv1 = __ldcs(xp + tstride);
    float4 xv2 = __ldcs(xp + 2 * tstride);
    float4 xv3 = __ldcs(xp + 3 * tstride);

    const float4 th = __ldg(&thresh[f]);
    const float4 dm = __ldg(&dtm[f]);

    float mx = dm.x * th.x;
    float my = dm.y * th.y;
    float mz = dm.z * th.z;
    float mw = dm.w * th.w;

    float4 sp;

    // t = 0
    mx += xv0.x; my += xv0.y; mz += xv0.z; mw += xv0.w;
    sp.x = (mx - th.x >= 0.0f) ? th.x : 0.0f;
    sp.y = (my - th.y >= 0.0f) ? th.y : 0.0f;
    sp.z = (mz - th.z >= 0.0f) ? th.z : 0.0f;
    sp.w = (mw - th.w >= 0.0f) ? th.w : 0.0f;
    mx -= sp.x; my -= sp.y; mz -= sp.z; mw -= sp.w;
    __stcs(op, sp);

    // t = 1
    mx += xv1.x; my += xv1.y; mz += xv1.z; mw += xv1.w;
    sp.x = (mx - th.x >= 0.0f) ? th.x : 0.0f;
    sp.y = (my - th.y >= 0.0f) ? th.y : 0.0f;
    sp.z = (mz - th.z >= 0.0f) ? th.z : 0.0f;
    sp.w = (mw - th.w >= 0.0f) ? th.w : 0.0f;
    mx -= sp.x; my -= sp.y; mz -= sp.z; mw -= sp.w;
    __stcs(op + tstride, sp);

    // t = 2
    mx += xv2.x; my += xv2.y; mz += xv2.z; mw += xv2.w;
    sp.x = (mx - th.x >= 0.0f) ? th.x : 0.0f;
    sp.y = (my - th.y >= 0.0f) ? th.y : 0.0f;
    sp.z = (mz - th.z >= 0.0f) ? th.z : 0.0f;
    sp.w = (mw - th.w >= 0.0f) ? th.w : 0.0f;
    mx -= sp.x; my -= sp.y; mz -= sp.z; mw -= sp.w;
    __stcs(op + 2 * tstride, sp);

    // t = 3
    mx += xv3.x; my += xv3.y; mz += xv3.z; mw += xv3.w;
    sp.x = (mx - th.x >= 0.0f) ? th.x : 0.0f;
    sp.y = (my - th.y >= 0.0f) ? th.y : 0.0f;
    sp.z = (mz - th.z >= 0.0f) ? th.z : 0.0f;
    sp.w = (mw - th.w >= 0.0f) ? th.w : 0.0f;
    mx -= sp.x; my -= sp.y; mz -= sp.z; mw -= sp.w;
    __stcs(op + 3 * tstride, sp);
}

extern "C" void kernel_launch(void* const* d_in, const int* in_sizes, int n_in,
                              void* d_out, int out_size)
{
    const float4* x      = (const float4*)d_in[0];
    const float4* thresh = (const float4*)d_in[1];
    const float4* dtm    = (const float4*)d_in[2];
    float4* out          = (float4*)d_out;

    const int threads = 256;
    const int blocks  = (N4 / threads) * B_BATCH;   // 24576 blocks
    if_fwd_kernel<<<blocks, threads>>>(x, thresh, dtm, out);
}

// round 10
// speedup vs baseline: 1.0082x; 1.0082x over previous
#include <cuda_runtime.h>
#include <cuda_bf16.h>

// IF spiking neuron forward (non-align, T>0):
//   x: [T, B, 1024, 3072] fp32 (flattened T*B), thresh2/dtmem: [1024,3072]
//   mem0 = dtmem*thre; per t: mem += x_t; spike = (mem>=thre)?thre:0; mem -= spike
//
// R10 = R7 body (best: 118.8us @ 6536 GB/s; batch in low-3 bid bits for L2
// param co-residence, all 4 t-loads front-batched, streaming hints) with
// 128-thread blocks: 49152 blocks, 16 blocks/SM (regs 32*128*16 = 65536,
// exact RF fit). Finer block granularity halves T_CTA -> halves the ~2-3us
// final-wave drain tail (24576-block config = 20.76 waves) and gives the
// work-stealing scheduler 2x finer units to balance across SMs/dies.
// BW itself is plateaued at ~6.53 TB/s for this 1:1 R/W mix (R4/R7/R9 all
// within 1%); this round trims scheduling overhead, not the stream.

#define T_STEPS 4
#define B_BATCH 8
#define FEAT_N  (1024u * 3072u)       // 3,145,728 feature elements
#define N4      (FEAT_N / 4u)         // 786,432 float4 per feature map
#define BLK     128u

__global__ __launch_bounds__(BLK, 16) void if_fwd_kernel(
    const float4* __restrict__ x,
    const float4* __restrict__ thresh,
    const float4* __restrict__ dtm,
    float4* __restrict__ out)
{
    const unsigned bid = blockIdx.x;
    const unsigned b   = bid & 7u;                         // batch index 0..7
    const unsigned f   = (bid >> 3) * BLK + threadIdx.x;   // feature float4 index
    if (f >= N4) return;

    const size_t tstride = (size_t)B_BATCH * N4;
    const float4* __restrict__ xp = x   + (size_t)b * N4 + f;
    float4* __restrict__       op = out + (size_t)b * N4 + f;

    // Front-batch ALL timestep loads (address-independent; only the membrane
    // recurrence is sequential, and that's pure compute).
    float4 xv0 = __ldcs(xp);
    float4 xv1 = __ldcs(xp + tstride);
    float4 xv2 = __ldcs(xp + 2 * tstride);
    float4 xv3 = __ldcs(xp + 3 * tstride);

    const float4 th = __ldg(&thresh[f]);
    const float4 dm = __ldg(&dtm[f]);

    float mx = dm.x * th.x;
    float my = dm.y * th.y;
    float mz = dm.z * th.z;
    float mw = dm.w * th.w;

    float4 sp;

    // t = 0
    mx += xv0.x; my += xv0.y; mz += xv0.z; mw += xv0.w;
    sp.x = (mx - th.x >= 0.0f) ? th.x : 0.0f;
    sp.y = (my - th.y >= 0.0f) ? th.y : 0.0f;
    sp.z = (mz - th.z >= 0.0f) ? th.z : 0.0f;
    sp.w = (mw - th.w >= 0.0f) ? th.w : 0.0f;
    mx -= sp.x; my -= sp.y; mz -= sp.z; mw -= sp.w;
    __stcs(op, sp);

    // t = 1
    mx += xv1.x; my += xv1.y; mz += xv1.z; mw += xv1.w;
    sp.x = (mx - th.x >= 0.0f) ? th.x : 0.0f;
    sp.y = (my - th.y >= 0.0f) ? th.y : 0.0f;
    sp.z = (mz - th.z >= 0.0f) ? th.z : 0.0f;
    sp.w = (mw - th.w >= 0.0f) ? th.w : 0.0f;
    mx -= sp.x; my -= sp.y; mz -= sp.z; mw -= sp.w;
    __stcs(op + tstride, sp);

    // t = 2
    mx += xv2.x; my += xv2.y; mz += xv2.z; mw += xv2.w;
    sp.x = (mx - th.x >= 0.0f) ? th.x : 0.0f;
    sp.y = (my - th.y >= 0.0f) ? th.y : 0.0f;
    sp.z = (mz - th.z >= 0.0f) ? th.z : 0.0f;
    sp.w = (mw - th.w >= 0.0f) ? th.w : 0.0f;
    mx -= sp.x; my -= sp.y; mz -= sp.z; mw -= sp.w;
    __stcs(op + 2 * tstride, sp);

    // t = 3
    mx += xv3.x; my += xv3.y; mz += xv3.z; mw += xv3.w;
    sp.x = (mx - th.x >= 0.0f) ? th.x : 0.0f;
    sp.y = (my - th.y >= 0.0f) ? th.y : 0.0f;
    sp.z = (mz - th.z >= 0.0f) ? th.z : 0.0f;
    sp.w = (mw - th.w >= 0.0f) ? th.w : 0.0f;
    mx -= sp.x; my -= sp.y; mz -= sp.z; mw -= sp.w;
    __stcs(op + 3 * tstride, sp);
}

extern "C" void kernel_launch(void* const* d_in, const int* in_sizes, int n_in,
                              void* d_out, int out_size)
{
    const float4* x      = (const float4*)d_in[0];
    const float4* thresh = (const float4*)d_in[1];
    const float4* dtm    = (const float4*)d_in[2];
    float4* out          = (float4*)d_out;

    const int blocks = (N4 / BLK) * B_BATCH;   // 49152 blocks
    if_fwd_kernel<<<blocks, BLK>>>(x, thresh, dtm, out);
}